// round 1
// baseline (speedup 1.0000x reference)
#include <cuda_runtime.h>
#include <cstddef>

#define N_NODES 50000
#define N_EDGES 800000
#define SCAN_TILE 512
#define N_TILES ((N_NODES + SCAN_TILE - 1) / SCAN_TILE)   // 98

// ---------------- scratch (static device allocations, allowed) ----------------
__device__ int   g_deg[N_NODES];
__device__ float g_norm[N_NODES];
__device__ int   g_rowstart[N_NODES + 1];
__device__ int   g_fill[N_NODES];
__device__ int   g_tilesum[128];
__device__ int   g_tileoff[128];
__device__ int   g_csr[N_EDGES];
__device__ float g_t1[N_NODES * 128];
__device__ float g_t2[N_NODES * 128];
__device__ float g_h1[N_NODES * 64];
__device__ float g_h2[N_NODES * 64];

// ---------------- CSR build ----------------
__global__ void zero_deg_kernel() {
    int i = blockIdx.x * blockDim.x + threadIdx.x;
    if (i < N_NODES) g_deg[i] = 0;
}

__global__ void hist_kernel(const int* __restrict__ dst) {
    int i = blockIdx.x * blockDim.x + threadIdx.x;
    if (i < N_EDGES) atomicAdd(&g_deg[dst[i]], 1);
}

__global__ void scan_tiles_kernel() {
    __shared__ int sh[SCAN_TILE];
    int t = threadIdx.x;
    int i = blockIdx.x * SCAN_TILE + t;
    int v = (i < N_NODES) ? g_deg[i] : 0;
    sh[t] = v;
    __syncthreads();
    #pragma unroll
    for (int off = 1; off < SCAN_TILE; off <<= 1) {
        int x = (t >= off) ? sh[t - off] : 0;
        __syncthreads();
        sh[t] += x;
        __syncthreads();
    }
    if (i < N_NODES) g_rowstart[i] = sh[t] - v;       // exclusive within tile
    if (t == SCAN_TILE - 1) g_tilesum[blockIdx.x] = sh[t];
}

__global__ void scan_sums_kernel() {
    if (threadIdx.x == 0 && blockIdx.x == 0) {
        int run = 0;
        for (int b = 0; b < N_TILES; b++) { g_tileoff[b] = run; run += g_tilesum[b]; }
        g_rowstart[N_NODES] = run;   // == N_EDGES
    }
}

__global__ void finalize_kernel() {
    int i = blockIdx.x * blockDim.x + threadIdx.x;
    if (i < N_NODES) {
        int rs = g_rowstart[i] + g_tileoff[i >> 9];
        g_rowstart[i] = rs;
        g_fill[i] = rs;
        float d = (float)g_deg[i];
        g_norm[i] = rsqrtf(d < 1.0f ? 1.0f : d);
    }
}

__global__ void fill_kernel(const int* __restrict__ src, const int* __restrict__ dst) {
    int i = blockIdx.x * blockDim.x + threadIdx.x;
    if (i < N_EDGES) {
        int p = atomicAdd(&g_fill[dst[i]], 1);
        g_csr[p] = src[i];
    }
}

// ---------------- propagation: out = sA * norm[n] * sum_{e in in(n)} X[src_e]*norm[src_e] + sB * add[n] ----------------
// One warp per node; lane owns V = F/32 contiguous features (vectorized).
template <int F>
__global__ void prop_kernel(const float* __restrict__ X,
                            const float* __restrict__ addt,
                            float sA, float sB,
                            float* __restrict__ out) {
    constexpr int V = F / 32;     // 4 (F=128) or 2 (F=64)
    int node = (blockIdx.x * blockDim.x + threadIdx.x) >> 5;
    if (node >= N_NODES) return;
    int lane = threadIdx.x & 31;
    int beg = g_rowstart[node];
    int end = g_rowstart[node + 1];

    float acc[V];
    #pragma unroll
    for (int i = 0; i < V; i++) acc[i] = 0.0f;

    int e = beg;
    for (; e + 4 <= end; e += 4) {
        int s0 = g_csr[e + 0], s1 = g_csr[e + 1], s2 = g_csr[e + 2], s3 = g_csr[e + 3];
        float n0 = g_norm[s0], n1 = g_norm[s1], n2 = g_norm[s2], n3 = g_norm[s3];
        if constexpr (V == 4) {
            float4 a0 = *(const float4*)(X + (size_t)s0 * F + lane * 4);
            float4 a1 = *(const float4*)(X + (size_t)s1 * F + lane * 4);
            float4 a2 = *(const float4*)(X + (size_t)s2 * F + lane * 4);
            float4 a3 = *(const float4*)(X + (size_t)s3 * F + lane * 4);
            acc[0] += a0.x * n0 + a1.x * n1 + a2.x * n2 + a3.x * n3;
            acc[1] += a0.y * n0 + a1.y * n1 + a2.y * n2 + a3.y * n3;
            acc[2] += a0.z * n0 + a1.z * n1 + a2.z * n2 + a3.z * n3;
            acc[3] += a0.w * n0 + a1.w * n1 + a2.w * n2 + a3.w * n3;
        } else {
            float2 a0 = *(const float2*)(X + (size_t)s0 * F + lane * 2);
            float2 a1 = *(const float2*)(X + (size_t)s1 * F + lane * 2);
            float2 a2 = *(const float2*)(X + (size_t)s2 * F + lane * 2);
            float2 a3 = *(const float2*)(X + (size_t)s3 * F + lane * 2);
            acc[0] += a0.x * n0 + a1.x * n1 + a2.x * n2 + a3.x * n3;
            acc[1] += a0.y * n0 + a1.y * n1 + a2.y * n2 + a3.y * n3;
        }
    }
    for (; e < end; e++) {
        int s = g_csr[e];
        float ns = g_norm[s];
        if constexpr (V == 4) {
            float4 a = *(const float4*)(X + (size_t)s * F + lane * 4);
            acc[0] += a.x * ns; acc[1] += a.y * ns; acc[2] += a.z * ns; acc[3] += a.w * ns;
        } else {
            float2 a = *(const float2*)(X + (size_t)s * F + lane * 2);
            acc[0] += a.x * ns; acc[1] += a.y * ns;
        }
    }

    float nd = g_norm[node];
    size_t base = (size_t)node * F + lane * V;
    if constexpr (V == 4) {
        float4 r;
        r.x = sA * nd * acc[0];
        r.y = sA * nd * acc[1];
        r.z = sA * nd * acc[2];
        r.w = sA * nd * acc[3];
        if (addt) {
            float4 ad = *(const float4*)(addt + base);
            r.x += sB * ad.x; r.y += sB * ad.y; r.z += sB * ad.z; r.w += sB * ad.w;
        }
        *(float4*)(out + base) = r;
    } else {
        float2 r;
        r.x = sA * nd * acc[0];
        r.y = sA * nd * acc[1];
        if (addt) {
            float2 ad = *(const float2*)(addt + base);
            r.x += sB * ad.x; r.y += sB * ad.y;
        }
        *(float2*)(out + base) = r;
    }
}

// ---------------- GEMM: out[n][o] = b[o] + sum_seg sum_f Xseg[n][f] * W[seg*F + f][o] ----------------
// Block tile: 64 nodes x FOUT outputs. Threads = (FOUT/8) * 16. Each thread: 4 nodes x 8 outputs.
// W staged per-segment into smem (max 32KB).
template <int F, int FOUT>
__global__ void gemm3_kernel(const float* __restrict__ X0,
                             const float* __restrict__ X1,
                             const float* __restrict__ X2,
                             const float* __restrict__ W,
                             const float* __restrict__ bias,
                             float* __restrict__ out) {
    constexpr int OG = FOUT / 8;
    constexpr int NT = OG * 16;
    __shared__ float Ws[F * FOUT];

    int tid = threadIdx.x;
    int og  = tid % OG;
    int ng  = tid / OG;            // [0,16)
    int obase = og * 8;
    int node0 = blockIdx.x * 64 + ng * 4;

    float acc[4][8];
    #pragma unroll
    for (int i = 0; i < 4; i++)
        #pragma unroll
        for (int j = 0; j < 8; j++) acc[i][j] = 0.0f;

    const float* segs[3] = {X0, X1, X2};

    // clamped row pointers (stores are guarded; loads just clamp to a valid row)
    const float* sp[4];

    for (int seg = 0; seg < 3; ++seg) {
        __syncthreads();
        const float* Wg = W + (size_t)seg * F * FOUT;
        for (int i = tid; i < F * FOUT; i += NT) Ws[i] = Wg[i];
        __syncthreads();

        const float* S = segs[seg];
        #pragma unroll
        for (int i = 0; i < 4; i++) {
            int n = node0 + i;
            if (n >= N_NODES) n = N_NODES - 1;
            sp[i] = S + (size_t)n * F;
        }

        for (int f = 0; f < F; ++f) {
            const float4* wp = (const float4*)(Ws + f * FOUT + obase);
            float4 wa = wp[0];
            float4 wb = wp[1];
            #pragma unroll
            for (int i = 0; i < 4; i++) {
                float xv = sp[i][f];
                acc[i][0] += xv * wa.x;
                acc[i][1] += xv * wa.y;
                acc[i][2] += xv * wa.z;
                acc[i][3] += xv * wa.w;
                acc[i][4] += xv * wb.x;
                acc[i][5] += xv * wb.y;
                acc[i][6] += xv * wb.z;
                acc[i][7] += xv * wb.w;
            }
        }
    }

    float4 ba = *(const float4*)(bias + obase);
    float4 bb = *(const float4*)(bias + obase + 4);
    #pragma unroll
    for (int i = 0; i < 4; i++) {
        int n = node0 + i;
        if (n < N_NODES) {
            float4 ra, rb;
            ra.x = acc[i][0] + ba.x; ra.y = acc[i][1] + ba.y;
            ra.z = acc[i][2] + ba.z; ra.w = acc[i][3] + ba.w;
            rb.x = acc[i][4] + bb.x; rb.y = acc[i][5] + bb.y;
            rb.z = acc[i][6] + bb.z; rb.w = acc[i][7] + bb.w;
            *(float4*)(out + (size_t)n * FOUT + obase)     = ra;
            *(float4*)(out + (size_t)n * FOUT + obase + 4) = rb;
        }
    }
}

// ---------------- host ----------------
extern "C" void kernel_launch(void* const* d_in, const int* in_sizes, int n_in,
                              void* d_out, int out_size) {
    const float* features = (const float*)d_in[0];   // [50000,128]
    const int*   src      = (const int*)d_in[1];     // [800000]
    const int*   dst      = (const int*)d_in[2];     // [800000]
    const float* W1       = (const float*)d_in[3];   // [384,64]
    const float* b1       = (const float*)d_in[4];   // [64]
    const float* W2       = (const float*)d_in[5];   // [192,64]
    const float* b2       = (const float*)d_in[6];   // [64]
    const float* W3       = (const float*)d_in[7];   // [192,40]
    const float* b3       = (const float*)d_in[8];   // [40]
    float* out            = (float*)d_out;           // [50000,40]

    float *t1, *t2, *h1, *h2;
    cudaGetSymbolAddress((void**)&t1, g_t1);
    cudaGetSymbolAddress((void**)&t2, g_t2);
    cudaGetSymbolAddress((void**)&h1, g_h1);
    cudaGetSymbolAddress((void**)&h2, g_h2);

    // ---- CSR build (dst-bucketed) ----
    zero_deg_kernel<<<(N_NODES + 255) / 256, 256>>>();
    hist_kernel<<<(N_EDGES + 255) / 256, 256>>>(dst);
    scan_tiles_kernel<<<N_TILES, SCAN_TILE>>>();
    scan_sums_kernel<<<1, 32>>>();
    finalize_kernel<<<(N_NODES + 255) / 256, 256>>>();
    fill_kernel<<<(N_EDGES + 255) / 256, 256>>>(src, dst);

    const int PROP_BLK = 256;                              // 8 warps = 8 nodes/block
    const int PROP_GRID = (N_NODES * 32 + PROP_BLK - 1) / PROP_BLK;
    const int GEMM_GRID = (N_NODES + 63) / 64;

    // ---- Layer 1: F=128 -> 64 ----
    prop_kernel<128><<<PROP_GRID, PROP_BLK>>>(features, nullptr, -1.0f, 0.0f, t1);
    prop_kernel<128><<<PROP_GRID, PROP_BLK>>>(t1, features, -2.0f, -1.0f, t2);
    gemm3_kernel<128, 64><<<GEMM_GRID, 128>>>(features, t1, t2, W1, b1, h1);

    // ---- Layer 2: F=64 -> 64 ----
    prop_kernel<64><<<PROP_GRID, PROP_BLK>>>(h1, nullptr, -1.0f, 0.0f, t1);
    prop_kernel<64><<<PROP_GRID, PROP_BLK>>>(t1, h1, -2.0f, -1.0f, t2);
    gemm3_kernel<64, 64><<<GEMM_GRID, 128>>>(h1, t1, t2, W2, b2, h2);

    // ---- Layer 3: F=64 -> 40 ----
    prop_kernel<64><<<PROP_GRID, PROP_BLK>>>(h2, nullptr, -1.0f, 0.0f, t1);
    prop_kernel<64><<<PROP_GRID, PROP_BLK>>>(t1, h2, -2.0f, -1.0f, t2);
    gemm3_kernel<64, 40><<<GEMM_GRID, 80>>>(h2, t1, t2, W3, b3, out);
}

// round 2
// speedup vs baseline: 1.7544x; 1.7544x over previous
#include <cuda_runtime.h>
#include <cstdint>
#include <cstddef>

#define N_NODES 50000
#define N_EDGES 800000
#define SCAN_TILE 512
#define N_TILES ((N_NODES + SCAN_TILE - 1) / SCAN_TILE)   // 98

// ---------------- scratch ----------------
__device__ int   g_deg[N_NODES];
__device__ float g_norm[N_NODES];
__device__ int   g_rowstart[N_NODES + 1];
__device__ int   g_fill[N_NODES];
__device__ int   g_tilesum[128];
__device__ int   g_tileoff[128];
__device__ int   g_csr[N_EDGES];
__device__ float g_t1[N_NODES * 128];
__device__ float g_t2[N_NODES * 128];
__device__ float g_h1[N_NODES * 64];
__device__ float g_h2[N_NODES * 64];

// ---------------- CSR build ----------------
__global__ void zero_deg_kernel() {
    int i = blockIdx.x * blockDim.x + threadIdx.x;
    if (i < N_NODES) g_deg[i] = 0;
}

__global__ void hist_kernel(const int* __restrict__ dst) {
    int i = blockIdx.x * blockDim.x + threadIdx.x;
    if (i < N_EDGES) atomicAdd(&g_deg[dst[i]], 1);
}

__global__ void scan_tiles_kernel() {
    __shared__ int sh[SCAN_TILE];
    int t = threadIdx.x;
    int i = blockIdx.x * SCAN_TILE + t;
    int v = (i < N_NODES) ? g_deg[i] : 0;
    sh[t] = v;
    __syncthreads();
    #pragma unroll
    for (int off = 1; off < SCAN_TILE; off <<= 1) {
        int x = (t >= off) ? sh[t - off] : 0;
        __syncthreads();
        sh[t] += x;
        __syncthreads();
    }
    if (i < N_NODES) g_rowstart[i] = sh[t] - v;       // exclusive within tile
    if (t == SCAN_TILE - 1) g_tilesum[blockIdx.x] = sh[t];
}

__global__ void scan_sums_kernel() {
    __shared__ int sh[128];
    int t = threadIdx.x;
    int v = (t < N_TILES) ? g_tilesum[t] : 0;
    sh[t] = v;
    __syncthreads();
    #pragma unroll
    for (int off = 1; off < 128; off <<= 1) {
        int x = (t >= off) ? sh[t - off] : 0;
        __syncthreads();
        sh[t] += x;
        __syncthreads();
    }
    if (t < N_TILES) g_tileoff[t] = sh[t] - v;        // exclusive
    if (t == 127) g_rowstart[N_NODES] = sh[127];
}

__global__ void finalize_kernel() {
    int i = blockIdx.x * blockDim.x + threadIdx.x;
    if (i < N_NODES) {
        int rs = g_rowstart[i] + g_tileoff[i >> 9];
        g_rowstart[i] = rs;
        g_fill[i] = rs;
        float d = (float)g_deg[i];
        g_norm[i] = rsqrtf(d < 1.0f ? 1.0f : d);
    }
}

__global__ void fill_kernel(const int* __restrict__ src, const int* __restrict__ dst) {
    int i = blockIdx.x * blockDim.x + threadIdx.x;
    if (i < N_EDGES) {
        int p = atomicAdd(&g_fill[dst[i]], 1);
        g_csr[p] = src[i];
    }
}

// ---------------- propagation ----------------
// out = sA * norm[n] * sum_{e in in(n)} X[src_e]*norm[src_e]  (+ sB * addt[n])
// F=128: 1 node/warp, lane owns float4. F=64: 2 nodes/warp, 16 lanes each own float4.
// Edge loop unrolled x8 for MLP.
template <int F>
__global__ void prop_kernel(const float* __restrict__ X,
                            const float* __restrict__ addt,
                            float sA, float sB,
                            float* __restrict__ out) {
    int gwarp = (blockIdx.x * blockDim.x + threadIdx.x) >> 5;
    int lane = threadIdx.x & 31;
    int node, sub;
    if constexpr (F == 128) { node = gwarp;              sub = lane;       }
    else                    { node = gwarp * 2 + (lane >> 4); sub = lane & 15; }
    if (node >= N_NODES) return;

    int beg = g_rowstart[node];
    int end = g_rowstart[node + 1];

    float4 acc = make_float4(0.f, 0.f, 0.f, 0.f);

    int e = beg;
    for (; e + 8 <= end; e += 8) {
        int s[8];
        #pragma unroll
        for (int j = 0; j < 8; j++) s[j] = g_csr[e + j];
        float nn[8];
        #pragma unroll
        for (int j = 0; j < 8; j++) nn[j] = g_norm[s[j]];
        float4 a[8];
        #pragma unroll
        for (int j = 0; j < 8; j++)
            a[j] = *(const float4*)(X + (size_t)s[j] * F + sub * 4);
        #pragma unroll
        for (int j = 0; j < 8; j++) {
            acc.x += a[j].x * nn[j];
            acc.y += a[j].y * nn[j];
            acc.z += a[j].z * nn[j];
            acc.w += a[j].w * nn[j];
        }
    }
    for (; e < end; e++) {
        int s = g_csr[e];
        float ns = g_norm[s];
        float4 a = *(const float4*)(X + (size_t)s * F + sub * 4);
        acc.x += a.x * ns; acc.y += a.y * ns; acc.z += a.z * ns; acc.w += a.w * ns;
    }

    float m = sA * g_norm[node];
    size_t base = (size_t)node * F + sub * 4;
    float4 r;
    r.x = m * acc.x; r.y = m * acc.y; r.z = m * acc.z; r.w = m * acc.w;
    if (addt) {
        float4 ad = *(const float4*)(addt + base);
        r.x += sB * ad.x; r.y += sB * ad.y; r.z += sB * ad.z; r.w += sB * ad.w;
    }
    *(float4*)(out + base) = r;
}

// ---------------- tf32 tensor-core GEMM ----------------
// out[M, FOUT] = bias + X0 @ W[0:F] + X1 @ W[F:2F] + X2 @ W[2F:3F]
// Block: 128 threads (4 warps). Warp tile: 32 rows (2x m16) x FOUT cols.
// mma.sync.aligned.m16n8k8 tf32.

__device__ __forceinline__ uint32_t f2tf32(float f) {
    uint32_t r;
    asm("cvt.rna.tf32.f32 %0, %1;" : "=r"(r) : "f"(f));
    return r;
}

__device__ __forceinline__ void mma_tf32(float* c, const uint32_t* a, uint32_t b0, uint32_t b1) {
    asm volatile(
        "mma.sync.aligned.m16n8k8.row.col.f32.tf32.tf32.f32 "
        "{%0,%1,%2,%3}, {%4,%5,%6,%7}, {%8,%9}, {%0,%1,%2,%3};"
        : "+f"(c[0]), "+f"(c[1]), "+f"(c[2]), "+f"(c[3])
        : "r"(a[0]), "r"(a[1]), "r"(a[2]), "r"(a[3]), "r"(b0), "r"(b1));
}

template <int F, int FOUT>
__global__ void gemm3_mma_kernel(const float* __restrict__ X0,
                                 const float* __restrict__ X1,
                                 const float* __restrict__ X2,
                                 const float* __restrict__ W,
                                 const float* __restrict__ bias,
                                 float* __restrict__ out) {
    constexpr int NT = FOUT / 8;       // n-tiles: 8 (FOUT=64) or 5 (FOUT=40)
    int warp = threadIdx.x >> 5;
    int lane = threadIdx.x & 31;
    int grp  = lane >> 2;              // 0..7
    int qid  = lane & 3;               // 0..3
    int r0 = blockIdx.x * 128 + warp * 32;

    float c[2][NT][4];
    #pragma unroll
    for (int t = 0; t < 2; t++)
        #pragma unroll
        for (int n = 0; n < NT; n++)
            #pragma unroll
            for (int j = 0; j < 4; j++) c[t][n][j] = 0.f;

    const float* segs[3] = {X0, X1, X2};

    #pragma unroll
    for (int seg = 0; seg < 3; ++seg) {
        const float* X  = segs[seg];
        const float* Wg = W + seg * F * FOUT;

        // clamped row pointers for the 4 fragment rows this thread touches
        int ra0 = r0 + grp;       if (ra0 >= N_NODES) ra0 = N_NODES - 1;
        int ra1 = r0 + grp + 8;   if (ra1 >= N_NODES) ra1 = N_NODES - 1;
        int ra2 = r0 + grp + 16;  if (ra2 >= N_NODES) ra2 = N_NODES - 1;
        int ra3 = r0 + grp + 24;  if (ra3 >= N_NODES) ra3 = N_NODES - 1;
        const float* p0 = X + (size_t)ra0 * F;
        const float* p1 = X + (size_t)ra1 * F;
        const float* p2 = X + (size_t)ra2 * F;
        const float* p3 = X + (size_t)ra3 * F;

        for (int k0 = 0; k0 < F; k0 += 8) {
            uint32_t A0[4], A1[4];
            A0[0] = f2tf32(p0[k0 + qid]);
            A0[1] = f2tf32(p1[k0 + qid]);
            A0[2] = f2tf32(p0[k0 + qid + 4]);
            A0[3] = f2tf32(p1[k0 + qid + 4]);
            A1[0] = f2tf32(p2[k0 + qid]);
            A1[1] = f2tf32(p3[k0 + qid]);
            A1[2] = f2tf32(p2[k0 + qid + 4]);
            A1[3] = f2tf32(p3[k0 + qid + 4]);

            const float* w0 = Wg + (k0 + qid) * FOUT + grp;
            const float* w1 = Wg + (k0 + qid + 4) * FOUT + grp;
            #pragma unroll
            for (int n = 0; n < NT; n++) {
                uint32_t b0 = f2tf32(w0[n * 8]);
                uint32_t b1 = f2tf32(w1[n * 8]);
                mma_tf32(c[0][n], A0, b0, b1);
                mma_tf32(c[1][n], A1, b0, b1);
            }
        }
    }

    // epilogue: c[t][n][0]=(row r0+t*16+grp, col n*8+2*qid), [1]=col+1,
    //           [2]=(row +8), [3]=(row +8, col+1)
    #pragma unroll
    for (int t = 0; t < 2; t++) {
        int rA = r0 + t * 16 + grp;
        int rB = rA + 8;
        #pragma unroll
        for (int n = 0; n < NT; n++) {
            int col = n * 8 + qid * 2;
            float bx = bias[col], by = bias[col + 1];
            if (rA < N_NODES) {
                float2 v = make_float2(c[t][n][0] + bx, c[t][n][1] + by);
                *(float2*)(out + (size_t)rA * FOUT + col) = v;
            }
            if (rB < N_NODES) {
                float2 v = make_float2(c[t][n][2] + bx, c[t][n][3] + by);
                *(float2*)(out + (size_t)rB * FOUT + col) = v;
            }
        }
    }
}

// ---------------- host ----------------
extern "C" void kernel_launch(void* const* d_in, const int* in_sizes, int n_in,
                              void* d_out, int out_size) {
    const float* features = (const float*)d_in[0];   // [50000,128]
    const int*   src      = (const int*)d_in[1];     // [800000]
    const int*   dst      = (const int*)d_in[2];     // [800000]
    const float* W1       = (const float*)d_in[3];   // [384,64]
    const float* b1       = (const float*)d_in[4];   // [64]
    const float* W2       = (const float*)d_in[5];   // [192,64]
    const float* b2       = (const float*)d_in[6];   // [64]
    const float* W3       = (const float*)d_in[7];   // [192,40]
    const float* b3       = (const float*)d_in[8];   // [40]
    float* out            = (float*)d_out;           // [50000,40]

    float *t1, *t2, *h1, *h2;
    cudaGetSymbolAddress((void**)&t1, g_t1);
    cudaGetSymbolAddress((void**)&t2, g_t2);
    cudaGetSymbolAddress((void**)&h1, g_h1);
    cudaGetSymbolAddress((void**)&h2, g_h2);

    // ---- CSR build (dst-bucketed) ----
    zero_deg_kernel<<<(N_NODES + 255) / 256, 256>>>();
    hist_kernel<<<(N_EDGES + 255) / 256, 256>>>(dst);
    scan_tiles_kernel<<<N_TILES, SCAN_TILE>>>();
    scan_sums_kernel<<<1, 128>>>();
    finalize_kernel<<<(N_NODES + 255) / 256, 256>>>();
    fill_kernel<<<(N_EDGES + 255) / 256, 256>>>(src, dst);

    const int PROP_BLK = 256;  // 8 warps
    const int GRID128 = (N_NODES + 7) / 8;            // 1 node/warp
    const int GRID64  = (N_NODES / 2 + 7) / 8;        // 2 nodes/warp
    const int GEMM_GRID = (N_NODES + 127) / 128;

    // ---- Layer 1: F=128 -> 64 ----
    prop_kernel<128><<<GRID128, PROP_BLK>>>(features, nullptr, -1.0f, 0.0f, t1);
    prop_kernel<128><<<GRID128, PROP_BLK>>>(t1, features, -2.0f, -1.0f, t2);
    gemm3_mma_kernel<128, 64><<<GEMM_GRID, 128>>>(features, t1, t2, W1, b1, h1);

    // ---- Layer 2: F=64 -> 64 ----
    prop_kernel<64><<<GRID64, PROP_BLK>>>(h1, nullptr, -1.0f, 0.0f, t1);
    prop_kernel<64><<<GRID64, PROP_BLK>>>(t1, h1, -2.0f, -1.0f, t2);
    gemm3_mma_kernel<64, 64><<<GEMM_GRID, 128>>>(h1, t1, t2, W2, b2, h2);

    // ---- Layer 3: F=64 -> 40 ----
    prop_kernel<64><<<GRID64, PROP_BLK>>>(h2, nullptr, -1.0f, 0.0f, t1);
    prop_kernel<64><<<GRID64, PROP_BLK>>>(t1, h2, -2.0f, -1.0f, t2);
    gemm3_mma_kernel<64, 40><<<GEMM_GRID, 128>>>(h2, t1, t2, W3, b3, out);
}